// round 9
// baseline (speedup 1.0000x reference)
#include <cuda_runtime.h>

// ---------------------------------------------------------------------------
// JLoss: j[b] = -sum_{i!=k} log(0.5 + 0.5*(S[b,i,i] - S[b,i,k]))
//   where S[b,i,k] = (sum over pixels p with target[b,p]==k of pred[b,i,p]) / n_k[b]
//
// Plan:
//   k_zero  : zero scratch T (B*C*C) and n (B*C)
//   k_hist  : n[b,k] = pixel count of class k in batch b
//   k_main  : T[b,i,k] via tiled, lane==channel segmented reduction
//   k_final : epilogue (logf + reduction) -> out[b]
// ---------------------------------------------------------------------------

#define C32   32
#define TILE  256
#define NW    8        // warps per block
#define TPB   256      // threads per block (main kernel)

// scratch (no cudaMalloc allowed)
__device__ float g_T[65536];   // B*C*C <= 8192 used
__device__ int   g_n[4096];    // B*C   <= 256 used

// shared layout (dynamic):
//   float s_tile[32][TILE+1]   : 32*257*4 = 32896 B
//   float s_acc [NW][32][32]   : 8*1024*4 = 32768 B
//   int   s_targ[TILE]         : 1024 B
#define SM_TILE_F   (32 * (TILE + 1))
#define SM_ACC_F    (NW * 32 * 32)
#define SMEM_BYTES  ((SM_TILE_F + SM_ACC_F) * 4 + TILE * 4)

__global__ void k_zero(int nT, int nN) {
    int i = blockIdx.x * blockDim.x + threadIdx.x;
    int stride = gridDim.x * blockDim.x;
    for (int x = i; x < nT; x += stride) g_T[x] = 0.0f;
    for (int x = i; x < nN; x += stride) g_n[x] = 0;
}

__global__ void k_hist(const int* __restrict__ targ, int HW) {
    __shared__ int h[C32];
    int b = blockIdx.y;
    if (threadIdx.x < C32) h[threadIdx.x] = 0;
    __syncthreads();
    int stride = gridDim.x * blockDim.x;
    for (int p = blockIdx.x * blockDim.x + threadIdx.x; p < HW; p += stride) {
        int k = targ[(size_t)b * HW + p];
        atomicAdd(&h[k], 1);
    }
    __syncthreads();
    if (threadIdx.x < C32) atomicAdd(&g_n[b * C32 + threadIdx.x], h[threadIdx.x]);
}

__device__ __forceinline__ void flush_acc(const float* s_acc, int b, int tid) {
    // s_acc[w][k][i] ; T layout: g_T[b*C*C + i*C + k]
    for (int kk = tid; kk < C32 * C32; kk += TPB) {
        float s = 0.0f;
        #pragma unroll
        for (int w = 0; w < NW; ++w) s += s_acc[w * (C32 * C32) + kk];
        int k = kk >> 5;
        int i = kk & 31;
        atomicAdd(&g_T[b * (C32 * C32) + i * C32 + k], s);
    }
}

__global__ void __launch_bounds__(TPB, 3)
k_main(const float* __restrict__ pred, const int* __restrict__ targ,
       int B, int HW, int tilesPerBatch) {
    extern __shared__ float sm[];
    float* s_tile = sm;                       // [32][TILE+1]
    float* s_acc  = sm + SM_TILE_F;           // [NW][32][32]
    int*   s_targ = (int*)(sm + SM_TILE_F + SM_ACC_F);  // [TILE]

    const int tid  = threadIdx.x;
    const int w    = tid >> 5;
    const int lane = tid & 31;

    // balanced contiguous tile chunks
    const int total = B * tilesPerBatch;
    const int G = gridDim.x;
    const int q = total / G, r = total % G;
    const int bi = blockIdx.x;
    const int t0 = bi * q + (bi < r ? bi : r);
    const int t1 = t0 + q + (bi < r ? 1 : 0);

    float* trow = s_tile + lane * (TILE + 1);       // this lane's channel row
    float* accw = s_acc + w * (C32 * C32) + lane;   // index by k*32

    int curb = -1;
    for (int t = t0; t < t1; ++t) {
        int b    = t / tilesPerBatch;
        int tile = t - b * tilesPerBatch;

        if (b != curb) {
            if (curb >= 0) {
                flush_acc(s_acc, curb, tid);
                __syncthreads();
            }
            for (int z = tid; z < NW * C32 * C32; z += TPB) s_acc[z] = 0.0f;
            curb = b;
        }

        const int p0 = tile * TILE;
        // stage target
        {
            int p = p0 + tid;
            s_targ[tid] = (p < HW) ? targ[(size_t)b * HW + p] : 0;
        }
        // stage pred tile: iteration c loads channel c, pixel tid (coalesced)
        const float* pb = pred + (size_t)b * C32 * HW + p0;
        if (p0 + TILE <= HW) {
            #pragma unroll 8
            for (int c = 0; c < C32; ++c)
                s_tile[c * (TILE + 1) + tid] = pb[(size_t)c * HW + tid];
        } else {
            int p = p0 + tid;
            #pragma unroll 8
            for (int c = 0; c < C32; ++c)
                s_tile[c * (TILE + 1) + tid] = (p < HW) ? pb[(size_t)c * HW + tid] : 0.0f;
        }
        __syncthreads();

        // warp w handles pixels [w*32, w*32+32); lane == channel
        const int jbase = w * 32;
        const int4* st4 = (const int4*)s_targ;
        #pragma unroll
        for (int qq = 0; qq < 8; ++qq) {
            int4 k4 = st4[(jbase >> 2) + qq];      // broadcast LDS.128
            float v0 = trow[jbase + 4 * qq + 0];
            float v1 = trow[jbase + 4 * qq + 1];
            float v2 = trow[jbase + 4 * qq + 2];
            float v3 = trow[jbase + 4 * qq + 3];
            accw[k4.x * 32] += v0;                 // conflict-free: bank == lane
            accw[k4.y * 32] += v1;
            accw[k4.z * 32] += v2;
            accw[k4.w * 32] += v3;
        }
        __syncthreads();
    }
    if (curb >= 0) flush_acc(s_acc, curb, tid);
}

__global__ void k_final(float* __restrict__ out) {
    const int b   = blockIdx.x;
    const int tid = threadIdx.x;          // 1024 threads
    const int i = tid >> 5;               // warp id
    const int k = tid & 31;               // lane

    __shared__ float s_diag[C32];
    __shared__ float s_red[C32];

    float nk = (float)g_n[b * C32 + k];
    float S  = g_T[b * (C32 * C32) + i * C32 + k] / nk;
    if (i == k) s_diag[i] = S;
    __syncthreads();

    float term = (i != k) ? logf(0.5f + 0.5f * (s_diag[i] - S)) : 0.0f;
    #pragma unroll
    for (int o = 16; o > 0; o >>= 1)
        term += __shfl_down_sync(0xFFFFFFFFu, term, o);
    if (k == 0) s_red[i] = term;
    __syncthreads();
    if (tid < 32) {
        float v = s_red[tid];
        #pragma unroll
        for (int o = 16; o > 0; o >>= 1)
            v += __shfl_down_sync(0xFFFFFFFFu, v, o);
        if (tid == 0) out[b] = -v;
    }
}

extern "C" void kernel_launch(void* const* d_in, const int* in_sizes, int n_in,
                              void* d_out, int out_size) {
    const float* pred = (const float*)d_in[0];
    const int*   targ = (const int*)d_in[1];
    float*       out  = (float*)d_out;

    const int B  = out_size;                   // j is (B,)
    const int HW = in_sizes[1] / B;            // target is (B,H,W)
    // C = in_sizes[0] / in_sizes[1] == 32 for this problem (design assumes 32)

    const int tilesPerBatch = (HW + TILE - 1) / TILE;
    const int total = B * tilesPerBatch;

    cudaFuncSetAttribute(k_main, cudaFuncAttributeMaxDynamicSharedMemorySize,
                         SMEM_BYTES);

    k_zero<<<4, 256>>>(B * C32 * C32, B * C32);

    dim3 hg(64, B);
    k_hist<<<hg, 256>>>(targ, HW);

    int grid = 444;                            // 148 SMs * 3 blocks
    if (grid > total) grid = total;
    k_main<<<grid, TPB, SMEM_BYTES>>>(pred, targ, B, HW, tilesPerBatch);

    k_final<<<B, C32 * C32>>>(out);
}

// round 10
// speedup vs baseline: 1.0315x; 1.0315x over previous
#include <cuda_runtime.h>

// ---------------------------------------------------------------------------
// JLoss: j[b] = -sum_{i!=k} log(0.5 + 0.5*(S[b,i,i] - S[b,i,k]))
//   where S[b,i,k] = (sum over pixels p with target[b,p]==k of pred[b,i,p]) / n_k[b]
//
// Plan:
//   k_zero  : zero scratch T (B*C*C) and n (B*C)
//   k_hist  : n[b,k] = pixel count of class k in batch b
//   k_main  : T[b,i,k] via tiled, lane==channel segmented reduction
//   k_final : epilogue (logf + reduction) -> out[b]
// ---------------------------------------------------------------------------

#define C32   32
#define TILE  256
#define NW    8        // warps per block
#define TPB   256      // threads per block (main kernel)

// scratch (no cudaMalloc allowed)
__device__ float g_T[65536];   // B*C*C <= 8192 used
__device__ int   g_n[4096];    // B*C   <= 256 used

// shared layout (dynamic):
//   float s_tile[32][TILE+1]   : 32*257*4 = 32896 B
//   float s_acc [NW][32][32]   : 8*1024*4 = 32768 B
//   int   s_targ[TILE]         : 1024 B
#define SM_TILE_F   (32 * (TILE + 1))
#define SM_ACC_F    (NW * 32 * 32)
#define SMEM_BYTES  ((SM_TILE_F + SM_ACC_F) * 4 + TILE * 4)

__global__ void k_zero(int nT, int nN) {
    int i = blockIdx.x * blockDim.x + threadIdx.x;
    int stride = gridDim.x * blockDim.x;
    for (int x = i; x < nT; x += stride) g_T[x] = 0.0f;
    for (int x = i; x < nN; x += stride) g_n[x] = 0;
}

__global__ void k_hist(const int* __restrict__ targ, int HW) {
    __shared__ int h[C32];
    int b = blockIdx.y;
    if (threadIdx.x < C32) h[threadIdx.x] = 0;
    __syncthreads();
    int stride = gridDim.x * blockDim.x;
    for (int p = blockIdx.x * blockDim.x + threadIdx.x; p < HW; p += stride) {
        int k = targ[(size_t)b * HW + p];
        atomicAdd(&h[k], 1);
    }
    __syncthreads();
    if (threadIdx.x < C32) atomicAdd(&g_n[b * C32 + threadIdx.x], h[threadIdx.x]);
}

__device__ __forceinline__ void flush_acc(const float* s_acc, int b, int tid) {
    // s_acc[w][k][i] ; T layout: g_T[b*C*C + i*C + k]
    for (int kk = tid; kk < C32 * C32; kk += TPB) {
        float s = 0.0f;
        #pragma unroll
        for (int w = 0; w < NW; ++w) s += s_acc[w * (C32 * C32) + kk];
        int k = kk >> 5;
        int i = kk & 31;
        atomicAdd(&g_T[b * (C32 * C32) + i * C32 + k], s);
    }
}

__global__ void __launch_bounds__(TPB, 3)
k_main(const float* __restrict__ pred, const int* __restrict__ targ,
       int B, int HW, int tilesPerBatch) {
    extern __shared__ float sm[];
    float* s_tile = sm;                       // [32][TILE+1]
    float* s_acc  = sm + SM_TILE_F;           // [NW][32][32]
    int*   s_targ = (int*)(sm + SM_TILE_F + SM_ACC_F);  // [TILE]

    const int tid  = threadIdx.x;
    const int w    = tid >> 5;
    const int lane = tid & 31;

    // balanced contiguous tile chunks
    const int total = B * tilesPerBatch;
    const int G = gridDim.x;
    const int q = total / G, r = total % G;
    const int bi = blockIdx.x;
    const int t0 = bi * q + (bi < r ? bi : r);
    const int t1 = t0 + q + (bi < r ? 1 : 0);

    float* trow = s_tile + lane * (TILE + 1);       // this lane's channel row
    float* accw = s_acc + w * (C32 * C32) + lane;   // index by k*32

    int curb = -1;
    for (int t = t0; t < t1; ++t) {
        int b    = t / tilesPerBatch;
        int tile = t - b * tilesPerBatch;

        if (b != curb) {
            if (curb >= 0) {
                flush_acc(s_acc, curb, tid);
                __syncthreads();
            }
            for (int z = tid; z < NW * C32 * C32; z += TPB) s_acc[z] = 0.0f;
            curb = b;
        }

        const int p0 = tile * TILE;
        // stage target
        {
            int p = p0 + tid;
            s_targ[tid] = (p < HW) ? targ[(size_t)b * HW + p] : 0;
        }
        // stage pred tile: iteration c loads channel c, pixel tid (coalesced)
        const float* pb = pred + (size_t)b * C32 * HW + p0;
        if (p0 + TILE <= HW) {
            #pragma unroll 8
            for (int c = 0; c < C32; ++c)
                s_tile[c * (TILE + 1) + tid] = pb[(size_t)c * HW + tid];
        } else {
            int p = p0 + tid;
            #pragma unroll 8
            for (int c = 0; c < C32; ++c)
                s_tile[c * (TILE + 1) + tid] = (p < HW) ? pb[(size_t)c * HW + tid] : 0.0f;
        }
        __syncthreads();

        // warp w handles pixels [w*32, w*32+32); lane == channel
        const int jbase = w * 32;
        const int4* st4 = (const int4*)s_targ;
        #pragma unroll
        for (int qq = 0; qq < 8; ++qq) {
            int4 k4 = st4[(jbase >> 2) + qq];      // broadcast LDS.128
            float v0 = trow[jbase + 4 * qq + 0];
            float v1 = trow[jbase + 4 * qq + 1];
            float v2 = trow[jbase + 4 * qq + 2];
            float v3 = trow[jbase + 4 * qq + 3];
            accw[k4.x * 32] += v0;                 // conflict-free: bank == lane
            accw[k4.y * 32] += v1;
            accw[k4.z * 32] += v2;
            accw[k4.w * 32] += v3;
        }
        __syncthreads();
    }
    if (curb >= 0) flush_acc(s_acc, curb, tid);
}

__global__ void k_final(float* __restrict__ out) {
    const int b   = blockIdx.x;
    const int tid = threadIdx.x;          // 1024 threads
    const int i = tid >> 5;               // warp id
    const int k = tid & 31;               // lane

    __shared__ float s_diag[C32];
    __shared__ float s_red[C32];

    float nk = (float)g_n[b * C32 + k];
    float S  = g_T[b * (C32 * C32) + i * C32 + k] / nk;
    if (i == k) s_diag[i] = S;
    __syncthreads();

    float term = (i != k) ? logf(0.5f + 0.5f * (s_diag[i] - S)) : 0.0f;
    #pragma unroll
    for (int o = 16; o > 0; o >>= 1)
        term += __shfl_down_sync(0xFFFFFFFFu, term, o);
    if (k == 0) s_red[i] = term;
    __syncthreads();
    if (tid < 32) {
        float v = s_red[tid];
        #pragma unroll
        for (int o = 16; o > 0; o >>= 1)
            v += __shfl_down_sync(0xFFFFFFFFu, v, o);
        if (tid == 0) out[b] = -v;
    }
}

extern "C" void kernel_launch(void* const* d_in, const int* in_sizes, int n_in,
                              void* d_out, int out_size) {
    const float* pred = (const float*)d_in[0];
    const int*   targ = (const int*)d_in[1];
    float*       out  = (float*)d_out;

    const int B  = out_size;                   // j is (B,)
    const int HW = in_sizes[1] / B;            // target is (B,H,W)
    // C = in_sizes[0] / in_sizes[1] == 32 for this problem (design assumes 32)

    const int tilesPerBatch = (HW + TILE - 1) / TILE;
    const int total = B * tilesPerBatch;

    cudaFuncSetAttribute(k_main, cudaFuncAttributeMaxDynamicSharedMemorySize,
                         SMEM_BYTES);

    k_zero<<<4, 256>>>(B * C32 * C32, B * C32);

    dim3 hg(64, B);
    k_hist<<<hg, 256>>>(targ, HW);

    int grid = 444;                            // 148 SMs * 3 blocks
    if (grid > total) grid = total;
    k_main<<<grid, TPB, SMEM_BYTES>>>(pred, targ, B, HW, tilesPerBatch);

    k_final<<<B, C32 * C32>>>(out);
}